// round 4
// baseline (speedup 1.0000x reference)
#include <cuda_runtime.h>
#include <cstdint>

// ---------------------------------------------------------------------------
// MultiHeadAttn: conv3x3(q/k/v) -> split heads (heads split SPATIAL dim) ->
// masked softmax attention over channel-tokens -> output projection.
// B=8, C=1024 (tokens), H=W=32 (spatial=1024), heads=16, d=64.
// ---------------------------------------------------------------------------

#define NCH   1024          // channels == tokens
#define NB    8
#define NHEAD 16
#define HDIM  64
#define WELEM (1024*1024*9) // 9437184

// Scratch (device globals; no allocation allowed)
__device__ float g_Wt_q[WELEM];
__device__ float g_Wt_k[WELEM];
__device__ float g_Wt_v[WELEM];
__device__ float g_Qh[NB*NCH*1024];   // [B,16,t,64]
__device__ float g_Kh[NB*NCH*1024];
__device__ float g_Vh[NB*NCH*1024];
__device__ float g_attn[NB*NCH*1024]; // [B,t,1024]

// ---------------------------------------------------------------------------
// Weight transpose: W[o,i,ky,kx] -> Wt[(((o/128)*1024 + i)*9 + tap)*128 + o%128]
// makes conv weight loads a fully coalesced linear stream per k-chunk.
// ---------------------------------------------------------------------------
__global__ void wtrans_kernel(const float* __restrict__ W, float* __restrict__ Wt)
{
    int idx = blockIdx.x * 256 + threadIdx.x;   // < 9437184
    int tap = idx % 9;
    int rem = idx / 9;
    int i   = rem & 1023;
    int o   = rem >> 10;
    Wt[(((size_t)(o >> 7) * 1024 + i) * 9 + tap) * 128 + (o & 127)] = W[idx];
}

// ---------------------------------------------------------------------------
// conv3x3 (SAME) as implicit GEMM.
// Block: 256 threads (16x16). Tile: 128 out-channels x 64 pixels (=2 rows = 1 head).
// Per-thread 8x4 register tile. K-chunk = 8 input channels.
// Input patch in smem: [8][4 rows][34 cols] zero-padded -> branch-free taps.
// Output written directly in head layout [B, head, o, d].
// ---------------------------------------------------------------------------
#define CKC 8
__global__ __launch_bounds__(256) void conv3x3_kernel(
    const float* __restrict__ x, const float* __restrict__ Wt,
    const float* __restrict__ bias, float* __restrict__ outH)
{
    __shared__ float sIn[CKC][136];        // 136 = 4*34
    __shared__ float sW[CKC * 9 * 128];

    const int b  = blockIdx.z;
    const int oy = blockIdx.y;             // out-channel tile (128 wide)
    const int pt = blockIdx.x;             // pixel tile == head index
    const int y0 = pt * 2;
    const int tid = threadIdx.x;
    const int tx = tid & 15, ty = tid >> 4;
    const int yl  = tx >> 3;               // 0/1: image row within tile
    const int xcb = (tx & 7) << 2;         // column base 0..28

    float acc[8][4];
    #pragma unroll
    for (int m = 0; m < 8; m++)
        #pragma unroll
        for (int n = 0; n < 4; n++) acc[m][n] = 0.f;

    const float* wt_base = Wt + (size_t)oy * (1024 * 9 * 128);
    const float* xb = x + (size_t)b * (NCH * 32 * 32);

    for (int i0 = 0; i0 < 1024; i0 += CKC) {
        // input patch: CKC channels x rows (y0-1..y0+2) x cols (-1..32), zero pad
        for (int idx = tid; idx < CKC * 136; idx += 256) {
            int i = idx / 136, rem = idx - i * 136;
            int r = rem / 34, c = rem - r * 34;
            int y = y0 - 1 + r, xx = c - 1;
            float v = 0.f;
            if ((unsigned)y < 32u && (unsigned)xx < 32u)
                v = xb[((i0 + i) * 32 + y) * 32 + xx];
            sIn[i][rem] = v;
        }
        // weights: contiguous float4 stream
        {
            const float4* ws = (const float4*)(wt_base + (size_t)i0 * (9 * 128));
            float4* sw4 = (float4*)sW;
            for (int idx = tid; idx < (CKC * 9 * 128) / 4; idx += 256)
                sw4[idx] = ws[idx];
        }
        __syncthreads();

        #pragma unroll
        for (int i = 0; i < CKC; i++) {
            #pragma unroll
            for (int dy = 0; dy < 3; dy++) {
                const float* rp = &sIn[i][(yl + dy) * 34 + xcb];
                float bw[6];
                #pragma unroll
                for (int j = 0; j < 6; j++) bw[j] = rp[j];
                #pragma unroll
                for (int dx = 0; dx < 3; dx++) {
                    const float* wp = &sW[((i * 9) + dy * 3 + dx) * 128 + ty * 8];
                    #pragma unroll
                    for (int mm = 0; mm < 8; mm++) {
                        float a = wp[mm];
                        acc[mm][0] += a * bw[dx + 0];
                        acc[mm][1] += a * bw[dx + 1];
                        acc[mm][2] += a * bw[dx + 2];
                        acc[mm][3] += a * bw[dx + 3];
                    }
                }
            }
        }
        __syncthreads();
    }

    // store into head layout: outH[((b*16 + head)*1024 + o)*64 + d]
    // pixel s = pt*64 + tx*4 + nn  ->  head = pt, d = tx*4+nn
    #pragma unroll
    for (int mm = 0; mm < 8; mm++) {
        int o = oy * 128 + ty * 8 + mm;
        float bo = bias[o];
        float4 r = make_float4(acc[mm][0] + bo, acc[mm][1] + bo,
                               acc[mm][2] + bo, acc[mm][3] + bo);
        *(float4*)(outH + (((size_t)b * 16 + pt) * 1024 + o) * 64 + tx * 4) = r;
    }
}

// ---------------------------------------------------------------------------
// Streaming-softmax attention. Block: 256 threads, one (b, h, 64-row t-tile).
// Q tile cached in smem (pre-scaled by 1/8); loop over 16 s-chunks of 64:
//   S = Q K^T, mask==0 -> -1e9, online softmax, O += P V.
// Thread tile 4x4; distributed cols use (tx + nn*16) for bank-conflict-free LDS.
// Dynamic smem: 4 * 64*65 floats = 66560 B.
// ---------------------------------------------------------------------------
__global__ __launch_bounds__(256) void attn_kernel(
    const float* __restrict__ Qh, const float* __restrict__ Kh,
    const float* __restrict__ Vh, const int* __restrict__ mask,
    float* __restrict__ out)
{
    extern __shared__ float sm[];
    float* sQ = sm;                 // [64][65]
    float* sK = sm + 64 * 65;
    float* sV = sm + 2 * 64 * 65;
    float* sP = sm + 3 * 64 * 65;

    const int b = blockIdx.z, h = blockIdx.y, t0 = blockIdx.x * 64;
    const int tid = threadIdx.x, tx = tid & 15, ty = tid >> 4;

    const size_t bh = ((size_t)b * 16 + h) * 1024 * 64;
    const float* Qb = Qh + bh;
    const float* Kb = Kh + bh;
    const float* Vb = Vh + bh;

    for (int idx = tid; idx < 64 * 64; idx += 256) {
        int r = idx >> 6, c = idx & 63;
        sQ[r * 65 + c] = Qb[(size_t)(t0 + r) * 64 + c] * 0.125f;
    }

    float m_i[4], l_i[4], O[4][4];
    #pragma unroll
    for (int mm = 0; mm < 4; mm++) {
        m_i[mm] = -1e30f; l_i[mm] = 0.f;
        #pragma unroll
        for (int nn = 0; nn < 4; nn++) O[mm][nn] = 0.f;
    }

    for (int s0 = 0; s0 < 1024; s0 += 64) {
        __syncthreads();   // prior PV done reading sK/sV/sP
        for (int idx = tid; idx < 64 * 64; idx += 256) {
            int r = idx >> 6, c = idx & 63;
            sK[r * 65 + c] = Kb[(size_t)(s0 + r) * 64 + c];
            sV[r * 65 + c] = Vb[(size_t)(s0 + r) * 64 + c];
        }
        __syncthreads();

        // S = Q K^T
        float S[4][4];
        #pragma unroll
        for (int mm = 0; mm < 4; mm++)
            #pragma unroll
            for (int nn = 0; nn < 4; nn++) S[mm][nn] = 0.f;

        #pragma unroll 8
        for (int k = 0; k < 64; k++) {
            float a[4], bb[4];
            #pragma unroll
            for (int mm = 0; mm < 4; mm++) a[mm] = sQ[(ty * 4 + mm) * 65 + k];
            #pragma unroll
            for (int nn = 0; nn < 4; nn++) bb[nn] = sK[(tx + nn * 16) * 65 + k];
            #pragma unroll
            for (int mm = 0; mm < 4; mm++)
                #pragma unroll
                for (int nn = 0; nn < 4; nn++) S[mm][nn] += a[mm] * bb[nn];
        }

        // mask (exact -1e9 to match reference)
        #pragma unroll
        for (int mm = 0; mm < 4; mm++) {
            const int* mrow = mask + ((size_t)b * 1024 + t0 + ty * 4 + mm) * 1024 + s0;
            #pragma unroll
            for (int nn = 0; nn < 4; nn++)
                if (mrow[tx + nn * 16] == 0) S[mm][nn] = -1e9f;
        }

        // online softmax (row reduce over the 16 tx lanes; ty pairs share a warp)
        #pragma unroll
        for (int mm = 0; mm < 4; mm++) {
            float mx = fmaxf(fmaxf(S[mm][0], S[mm][1]), fmaxf(S[mm][2], S[mm][3]));
            #pragma unroll
            for (int off = 8; off >= 1; off >>= 1)
                mx = fmaxf(mx, __shfl_xor_sync(0xffffffffu, mx, off));
            float mnew = fmaxf(m_i[mm], mx);
            float corr = __expf(m_i[mm] - mnew);
            float rs = 0.f;
            #pragma unroll
            for (int nn = 0; nn < 4; nn++) {
                float p = __expf(S[mm][nn] - mnew);
                S[mm][nn] = p;
                rs += p;
            }
            #pragma unroll
            for (int off = 8; off >= 1; off >>= 1)
                rs += __shfl_xor_sync(0xffffffffu, rs, off);
            l_i[mm] = l_i[mm] * corr + rs;
            m_i[mm] = mnew;
            #pragma unroll
            for (int nn = 0; nn < 4; nn++) O[mm][nn] *= corr;
            #pragma unroll
            for (int nn = 0; nn < 4; nn++)
                sP[(ty * 4 + mm) * 65 + tx + nn * 16] = S[mm][nn];
        }
        __syncthreads();

        // O += P V
        #pragma unroll 8
        for (int k = 0; k < 64; k++) {
            float a[4], bb[4];
            #pragma unroll
            for (int mm = 0; mm < 4; mm++) a[mm] = sP[(ty * 4 + mm) * 65 + k];
            #pragma unroll
            for (int nn = 0; nn < 4; nn++) bb[nn] = sV[k * 65 + tx + nn * 16];
            #pragma unroll
            for (int mm = 0; mm < 4; mm++)
                #pragma unroll
                for (int nn = 0; nn < 4; nn++) O[mm][nn] += a[mm] * bb[nn];
        }
    }

    #pragma unroll
    for (int mm = 0; mm < 4; mm++) {
        float inv = 1.f / l_i[mm];
        int t = t0 + ty * 4 + mm;
        #pragma unroll
        for (int nn = 0; nn < 4; nn++)
            out[((size_t)b * 1024 + t) * 1024 + h * 64 + tx + nn * 16] = O[mm][nn] * inv;
    }
}

// ---------------------------------------------------------------------------
// Output projection: out[m, n] = sum_k A[m,k] * Wo[n,k] + bo[n]
// M = 8192 (b*t), N = 1024, K = 1024. 64x64 tiles, BK=16, 4x4 per thread.
// ---------------------------------------------------------------------------
__global__ __launch_bounds__(256) void proj_kernel(
    const float* __restrict__ A, const float* __restrict__ Wo,
    const float* __restrict__ bo, float* __restrict__ out)
{
    __shared__ float sA[64][17];
    __shared__ float sB[64][17];
    const int m0 = blockIdx.y * 64, n0 = blockIdx.x * 64;
    const int tid = threadIdx.x, tx = tid & 15, ty = tid >> 4;

    float acc[4][4];
    #pragma unroll
    for (int mm = 0; mm < 4; mm++)
        #pragma unroll
        for (int nn = 0; nn < 4; nn++) acc[mm][nn] = 0.f;

    for (int k0 = 0; k0 < 1024; k0 += 16) {
        for (int idx = tid; idx < 1024; idx += 256) {
            int r = idx >> 4, c = idx & 15;
            sA[r][c] = A[(size_t)(m0 + r) * 1024 + k0 + c];
            sB[r][c] = Wo[(size_t)(n0 + r) * 1024 + k0 + c];
        }
        __syncthreads();
        #pragma unroll
        for (int kk = 0; kk < 16; kk++) {
            float a[4], bb[4];
            #pragma unroll
            for (int mm = 0; mm < 4; mm++) a[mm] = sA[ty * 4 + mm][kk];
            #pragma unroll
            for (int nn = 0; nn < 4; nn++) bb[nn] = sB[tx + nn * 16][kk];
            #pragma unroll
            for (int mm = 0; mm < 4; mm++)
                #pragma unroll
                for (int nn = 0; nn < 4; nn++) acc[mm][nn] += a[mm] * bb[nn];
        }
        __syncthreads();
    }

    #pragma unroll
    for (int mm = 0; mm < 4; mm++)
        #pragma unroll
        for (int nn = 0; nn < 4; nn++)
            out[(size_t)(m0 + ty * 4 + mm) * 1024 + n0 + tx + nn * 16] =
                acc[mm][nn] + bo[n0 + tx + nn * 16];
}

// ---------------------------------------------------------------------------
extern "C" void kernel_launch(void* const* d_in, const int* in_sizes, int n_in,
                              void* d_out, int out_size)
{
    const float* q   = (const float*)d_in[0];
    const float* k   = (const float*)d_in[1];
    const float* v   = (const float*)d_in[2];
    const float* Wq  = (const float*)d_in[3];
    const float* bq  = (const float*)d_in[4];
    const float* Wk  = (const float*)d_in[5];
    const float* bk  = (const float*)d_in[6];
    const float* Wv  = (const float*)d_in[7];
    const float* bv  = (const float*)d_in[8];
    const float* Wo  = (const float*)d_in[9];
    const float* bo  = (const float*)d_in[10];
    const int*   msk = (const int*)d_in[11];
    float* out = (float*)d_out;

    float *wtq, *wtk, *wtv, *qh, *kh, *vh, *attn;
    cudaGetSymbolAddress((void**)&wtq, g_Wt_q);
    cudaGetSymbolAddress((void**)&wtk, g_Wt_k);
    cudaGetSymbolAddress((void**)&wtv, g_Wt_v);
    cudaGetSymbolAddress((void**)&qh,  g_Qh);
    cudaGetSymbolAddress((void**)&kh,  g_Kh);
    cudaGetSymbolAddress((void**)&vh,  g_Vh);
    cudaGetSymbolAddress((void**)&attn, g_attn);

    // 1) weight relayout (one-time cost per replay, ~bandwidth bound, tiny)
    wtrans_kernel<<<WELEM / 256, 256>>>(Wq, wtq);
    wtrans_kernel<<<WELEM / 256, 256>>>(Wk, wtk);
    wtrans_kernel<<<WELEM / 256, 256>>>(Wv, wtv);

    // 2) convs -> head layout
    dim3 cg(16, 8, NB);
    conv3x3_kernel<<<cg, 256>>>(q, wtq, bq, qh);
    conv3x3_kernel<<<cg, 256>>>(k, wtk, bk, kh);
    conv3x3_kernel<<<cg, 256>>>(v, wtv, bv, vh);

    // 3) attention
    cudaFuncSetAttribute(attn_kernel, cudaFuncAttributeMaxDynamicSharedMemorySize, 66560);
    attn_kernel<<<dim3(16, NHEAD, NB), 256, 66560>>>(qh, kh, vh, msk, attn);

    // 4) projection
    proj_kernel<<<dim3(16, 128), 256>>>(attn, Wo, bo, out);
}

// round 6
// speedup vs baseline: 1.7124x; 1.7124x over previous
#include <cuda_runtime.h>
#include <cuda_bf16.h>
#include <cstdint>

// ---------------------------------------------------------------------------
// MultiHeadAttn: conv3x3(q/k/v) via tf32 mma.sync implicit GEMM -> split heads
// -> masked softmax attention over channel-tokens -> output projection.
// B=8, C=1024 (tokens), H=W=32 (spatial=1024), heads=16, d=64.
// NOTE: harness PTX target is plain sm_103 (no 'a') -> tcgen05 unavailable;
// warp-level mma.sync (HMMA) is the tensor-core path that encodes there.
// ---------------------------------------------------------------------------

#define NCH   1024
#define NB    8
#define NHEAD 16
#define KC    9216            // 9 taps * 1024 channels

// ---------------- device scratch (no allocation allowed) -------------------
__device__ float g_Wt_q[(size_t)1024 * KC];   // [o][tap*1024+i], tf32-rounded
__device__ float g_Wt_k[(size_t)1024 * KC];
__device__ float g_Wt_v[(size_t)1024 * KC];
__device__ float g_Xt_q[(size_t)NB * 1024 * 1024]; // [b][p][i], tf32-rounded
__device__ float g_Xt_k[(size_t)NB * 1024 * 1024];
__device__ float g_Xt_v[(size_t)NB * 1024 * 1024];
__device__ float g_Qh[NB * NCH * 1024];    // [B,16,t,64]
__device__ float g_Kh[NB * NCH * 1024];
__device__ float g_Vh[NB * NCH * 1024];
__device__ float g_attn[NB * NCH * 1024];  // [B,t,1024]

// ---------------- helpers ---------------------------------------------------
__device__ __forceinline__ uint32_t smem_u32(const void* p) {
    uint32_t a;
    asm("{ .reg .u64 t; cvta.to.shared.u64 t, %1; cvt.u32.u64 %0, t; }"
        : "=r"(a) : "l"(p));
    return a;
}
__device__ __forceinline__ float to_tf32(float v) {
    float o;
    asm("cvt.rna.tf32.f32 %0, %1;" : "=f"(o) : "f"(v));
    return o;
}
__device__ __forceinline__ void cp16(uint32_t dst, const void* src, int sz) {
    asm volatile("cp.async.ca.shared.global [%0], [%1], 16, %2;"
                 :: "r"(dst), "l"(src), "r"(sz) : "memory");
}
__device__ __forceinline__ void cp_commit() {
    asm volatile("cp.async.commit_group;" ::: "memory");
}
__device__ __forceinline__ void cp_wait0() {
    asm volatile("cp.async.wait_group 0;" ::: "memory");
}
__device__ __forceinline__ void mma_tf32(float& d0, float& d1, float& d2, float& d3,
                                         uint32_t a0, uint32_t a1, uint32_t a2, uint32_t a3,
                                         uint32_t b0, uint32_t b1) {
    asm volatile(
        "mma.sync.aligned.m16n8k8.row.col.f32.tf32.tf32.f32 "
        "{%0,%1,%2,%3}, {%4,%5,%6,%7}, {%8,%9}, {%0,%1,%2,%3};"
        : "+f"(d0), "+f"(d1), "+f"(d2), "+f"(d3)
        : "r"(a0), "r"(a1), "r"(a2), "r"(a3), "r"(b0), "r"(b1));
}

// ---------------------------------------------------------------------------
// Weight prep: W[o,i,tap] -> Wt[o][tap*1024 + i]  (tf32-rounded)
// ---------------------------------------------------------------------------
__global__ void wprep_kernel(const float* __restrict__ W, float* __restrict__ Wt)
{
    int idx = blockIdx.x * 256 + threadIdx.x;     // o*9216 + i*9 + tap
    int tap = idx % 9;
    int rem = idx / 9;
    int i = rem & 1023;
    int o = rem >> 10;
    Wt[(size_t)o * KC + tap * 1024 + i] = to_tf32(W[idx]);
}

// ---------------------------------------------------------------------------
// Input prep (transpose): x[b,i,p] -> Xt[b][p][i]  (tf32-rounded)
// ---------------------------------------------------------------------------
__global__ void xprep_kernel(const float* __restrict__ x, float* __restrict__ Xt)
{
    int idx = blockIdx.x * 256 + threadIdx.x;     // b*1M + i*1024 + p
    int p = idx & 1023;
    int rem = idx >> 10;
    int i = rem & 1023;
    int b = rem >> 10;
    Xt[(((size_t)b << 10) + p) * 1024 + i] = to_tf32(x[idx]);
}

// ---------------------------------------------------------------------------
// tf32 tensor-core conv GEMM.
// CTA: 128 out-channels (M) x 128 pixels (N), K = 9*1024 in 576 steps of 16.
// 8 warps as 2(M)x4(N); warp tile 64x32 via m16n8k8 (4 m-tiles x 4 n-tiles).
// Double-buffered cp.async SMEM, rows padded to 20 floats (16B-aligned,
// conflict-free fragment LDS). Border taps zero-filled (src-size=0).
// Output in head layout [B,16,t=oc,d=p&63].
// ---------------------------------------------------------------------------
__global__ __launch_bounds__(256, 2) void conv_tc_kernel(
    const float* __restrict__ Wt, const float* __restrict__ Xt,
    const float* __restrict__ bias, float* __restrict__ outH)
{
    __shared__ float sA[2][128][20];
    __shared__ float sB[2][128][20];

    const int b  = blockIdx.z;
    const int m0 = blockIdx.y * 128;   // out-channel base
    const int n0 = blockIdx.x * 128;   // pixel base
    const int tid = threadIdx.x;
    const int wid = tid >> 5, lane = tid & 31;
    const int gid = lane >> 2, tig = lane & 3;
    const int wm = wid >> 2, wn = wid & 3;       // 2 x 4 warp grid

    const float* Wb = Wt + (size_t)m0 * KC;
    const float* Xb = Xt + ((size_t)b << 20);

    float acc[4][4][4];
    #pragma unroll
    for (int mt = 0; mt < 4; mt++)
        #pragma unroll
        for (int nt = 0; nt < 4; nt++)
            #pragma unroll
            for (int r = 0; r < 4; r++) acc[mt][nt][r] = 0.f;

    // step loader: s = tap*64 + kc ; loads A 128x16 and B 128x16 into buf bs
    auto load_step = [&](int s, int bs) {
        const int tap = s >> 6, kc = s & 63;
        const int k0 = kc * 16;
        const int dy = tap / 3 - 1, dx = tap % 3 - 1;
        #pragma unroll
        for (int it = 0; it < 2; it++) {         // A: 512 float4
            int idx = tid * 2 + it;
            int row = idx >> 2, c4 = idx & 3;
            uint32_t dst = smem_u32(&sA[bs][row][c4 * 4]);
            cp16(dst, Wb + (size_t)row * KC + tap * 1024 + k0 + c4 * 4, 16);
        }
        #pragma unroll
        for (int it = 0; it < 2; it++) {         // B: 512 float4
            int idx = tid * 2 + it;
            int row = idx >> 2, c4 = idx & 3;
            int p = n0 + row;
            int ys = (p >> 5) + dy, xs = (p & 31) + dx;
            bool ok = ((unsigned)ys < 32u) && ((unsigned)xs < 32u);
            int pp = ok ? (ys * 32 + xs) : 0;
            uint32_t dst = smem_u32(&sB[bs][row][c4 * 4]);
            cp16(dst, Xb + (size_t)pp * 1024 + k0 + c4 * 4, ok ? 16 : 0);
        }
    };

    load_step(0, 0);
    cp_commit();

    for (int s = 0; s < 576; s++) {
        const int bs = s & 1;
        cp_wait0();
        __syncthreads();
        if (s + 1 < 576) { load_step(s + 1, bs ^ 1); cp_commit(); }

        #pragma unroll
        for (int kb = 0; kb < 16; kb += 8) {
            uint32_t af[4][4], bf[4][2];
            #pragma unroll
            for (int mt = 0; mt < 4; mt++) {
                int r0 = wm * 64 + mt * 16 + gid;
                af[mt][0] = __float_as_uint(sA[bs][r0][kb + tig]);
                af[mt][1] = __float_as_uint(sA[bs][r0 + 8][kb + tig]);
                af[mt][2] = __float_as_uint(sA[bs][r0][kb + tig + 4]);
                af[mt][3] = __float_as_uint(sA[bs][r0 + 8][kb + tig + 4]);
            }
            #pragma unroll
            for (int nt = 0; nt < 4; nt++) {
                int c0 = wn * 32 + nt * 8 + gid;
                bf[nt][0] = __float_as_uint(sB[bs][c0][kb + tig]);
                bf[nt][1] = __float_as_uint(sB[bs][c0][kb + tig + 4]);
            }
            #pragma unroll
            for (int mt = 0; mt < 4; mt++)
                #pragma unroll
                for (int nt = 0; nt < 4; nt++)
                    mma_tf32(acc[mt][nt][0], acc[mt][nt][1],
                             acc[mt][nt][2], acc[mt][nt][3],
                             af[mt][0], af[mt][1], af[mt][2], af[mt][3],
                             bf[nt][0], bf[nt][1]);
        }
        __syncthreads();
    }

    // epilogue -> head layout  outH[((b*16 + p>>6)*1024 + oc)*64 + (p&63)]
    #pragma unroll
    for (int mt = 0; mt < 4; mt++) {
        int r0 = m0 + wm * 64 + mt * 16 + gid;    // oc rows r0, r0+8
        float bv0 = bias[r0], bv1 = bias[r0 + 8];
        #pragma unroll
        for (int nt = 0; nt < 4; nt++) {
            int p = n0 + wn * 32 + nt * 8 + tig * 2;   // pixel (even)
            size_t base = ((size_t)b * 16 + (p >> 6)) * 1024;
            size_t i00 = (base + r0) * 64 + (p & 63);
            size_t i10 = (base + r0 + 8) * 64 + (p & 63);
            outH[i00]     = acc[mt][nt][0] + bv0;
            outH[i00 + 1] = acc[mt][nt][1] + bv0;
            outH[i10]     = acc[mt][nt][2] + bv1;
            outH[i10 + 1] = acc[mt][nt][3] + bv1;
        }
    }
}

// ---------------------------------------------------------------------------
// Streaming-softmax attention (unchanged from passing kernel).
// ---------------------------------------------------------------------------
__global__ __launch_bounds__(256) void attn_kernel(
    const float* __restrict__ Qh, const float* __restrict__ Kh,
    const float* __restrict__ Vh, const int* __restrict__ mask,
    float* __restrict__ out)
{
    extern __shared__ float sm[];
    float* sQ = sm;
    float* sK = sm + 64 * 65;
    float* sV = sm + 2 * 64 * 65;
    float* sP = sm + 3 * 64 * 65;

    const int b = blockIdx.z, h = blockIdx.y, t0 = blockIdx.x * 64;
    const int tid = threadIdx.x, tx = tid & 15, ty = tid >> 4;

    const size_t bh = ((size_t)b * 16 + h) * 1024 * 64;
    const float* Qb = Qh + bh;
    const float* Kb = Kh + bh;
    const float* Vb = Vh + bh;

    for (int idx = tid; idx < 64 * 64; idx += 256) {
        int r = idx >> 6, c = idx & 63;
        sQ[r * 65 + c] = Qb[(size_t)(t0 + r) * 64 + c] * 0.125f;
    }

    float m_i[4], l_i[4], O[4][4];
    #pragma unroll
    for (int mm = 0; mm < 4; mm++) {
        m_i[mm] = -1e30f; l_i[mm] = 0.f;
        #pragma unroll
        for (int nn = 0; nn < 4; nn++) O[mm][nn] = 0.f;
    }

    for (int s0 = 0; s0 < 1024; s0 += 64) {
        __syncthreads();
        for (int idx = tid; idx < 64 * 64; idx += 256) {
            int r = idx >> 6, c = idx & 63;
            sK[r * 65 + c] = Kb[(size_t)(s0 + r) * 64 + c];
            sV[r * 65 + c] = Vb[(size_t)(s0 + r) * 64 + c];
        }
        __syncthreads();

        float S[4][4];
        #pragma unroll
        for (int mm = 0; mm < 4; mm++)
            #pragma unroll
            for (int nn = 0; nn < 4; nn++) S[mm][nn] = 0.f;

        #pragma unroll 8
        for (int k = 0; k < 64; k++) {
            float a[4], bb[4];
            #pragma unroll
            for (int mm = 0; mm < 4; mm++) a[mm] = sQ[(ty * 4 + mm) * 65 + k];
            #pragma unroll
            for (int nn = 0; nn < 4; nn++) bb[nn] = sK[(tx + nn * 16) * 65 + k];
            #pragma unroll
            for (int mm = 0; mm < 4; mm++)
                #pragma unroll
                for (int nn = 0; nn < 4; nn++) S[mm][nn] += a[mm] * bb[nn];
        }

        #pragma unroll
        for (int mm = 0; mm < 4; mm++) {
            const int* mrow = mask + ((size_t)b * 1024 + t0 + ty * 4 + mm) * 1024 + s0;
            #pragma unroll
            for (int nn = 0; nn < 4; nn++)
                if (mrow[tx + nn * 16] == 0) S[mm][nn] = -1e9f;
        }

        #pragma unroll
        for (int mm = 0; mm < 4; mm++) {
            float mx = fmaxf(fmaxf(S[mm][0], S[mm][1]), fmaxf(S[mm][2], S[mm][3]));
            #pragma unroll
            for (int off = 8; off >= 1; off >>= 1)
                mx = fmaxf(mx, __shfl_xor_sync(0xffffffffu, mx, off));
            float mnew = fmaxf(m_i[mm], mx);
            float corr = __expf(m_i[mm] - mnew);
            float rs = 0.f;
            #pragma unroll
            for (int nn = 0; nn < 4; nn++) {
                float p = __expf(S[mm][nn] - mnew);
                S[mm][nn] = p;
                rs += p;
            }
            #pragma unroll
            for (int off = 8; off >= 1; off >>= 1)
                rs += __shfl_xor_sync(0xffffffffu, rs, off);
            l_i[mm] = l_i[mm] * corr + rs;
            m_i[mm] = mnew;
            #pragma unroll
            for (int nn = 0; nn < 4; nn++) O[mm][nn] *= corr;
            #pragma unroll
            for (int nn = 0; nn < 4; nn++)
                sP[(ty * 4 + mm) * 65 + tx + nn * 16] = S[mm][nn];
        }
        __syncthreads();

        #pragma unroll 8
        for (int k = 0; k < 64; k++) {
            float a[4], bb[4];
            #pragma unroll
            for (int mm = 0; mm < 4; mm++) a[mm] = sP[(ty * 4 + mm) * 65 + k];
            #pragma unroll
            for (int nn = 0; nn < 4; nn++) bb[nn] = sV[k * 65 + tx + nn * 16];
            #pragma unroll
            for (int mm = 0; mm < 4; mm++)
                #pragma unroll
                for (int nn = 0; nn < 4; nn++) O[mm][nn] += a[mm] * bb[nn];
        }
    }

    #pragma unroll
    for (int mm = 0; mm < 4; mm++) {
        float inv = 1.f / l_i[mm];
        int t = t0 + ty * 4 + mm;
        #pragma unroll
        for (int nn = 0; nn < 4; nn++)
            out[((size_t)b * 1024 + t) * 1024 + h * 64 + tx + nn * 16] = O[mm][nn] * inv;
    }
}

// ---------------------------------------------------------------------------
// Output projection (unchanged).
// ---------------------------------------------------------------------------
__global__ __launch_bounds__(256) void proj_kernel(
    const float* __restrict__ A, const float* __restrict__ Wo,
    const float* __restrict__ bo, float* __restrict__ out)
{
    __shared__ float sA[64][17];
    __shared__ float sB[64][17];
    const int m0 = blockIdx.y * 64, n0 = blockIdx.x * 64;
    const int tid = threadIdx.x, tx = tid & 15, ty = tid >> 4;

    float acc[4][4];
    #pragma unroll
    for (int mm = 0; mm < 4; mm++)
        #pragma unroll
        for (int nn = 0; nn < 4; nn++) acc[mm][nn] = 0.f;

    for (int k0 = 0; k0 < 1024; k0 += 16) {
        for (int idx = tid; idx < 1024; idx += 256) {
            int r = idx >> 4, c = idx & 15;
            sA[r][c] = A[(size_t)(m0 + r) * 1024 + k0 + c];
            sB[r][c] = Wo[(size_t)(n0 + r) * 1024 + k0 + c];
        }
        __syncthreads();
        #pragma unroll
        for (int kk = 0; kk < 16; kk++) {
            float a[4], bb[4];
            #pragma unroll
            for (int mm = 0; mm < 4; mm++) a[mm] = sA[ty * 4 + mm][kk];
            #pragma unroll
            for (int nn = 0; nn < 4; nn++) bb[nn] = sB[tx + nn * 16][kk];
            #pragma unroll
            for (int mm = 0; mm < 4; mm++)
                #pragma unroll
                for (int nn = 0; nn < 4; nn++) acc[mm][nn] += a[mm] * bb[nn];
        }
        __syncthreads();
    }

    #pragma unroll
    for (int mm = 0; mm < 4; mm++)
        #pragma unroll
        for (int nn = 0; nn < 4; nn++)
            out[(size_t)(m0 + ty * 4 + mm) * 1024 + n0 + tx + nn * 16] =
                acc[mm][nn] + bo[n0 + tx + nn * 16];
}

// ---------------------------------------------------------------------------
extern "C" void kernel_launch(void* const* d_in, const int* in_sizes, int n_in,
                              void* d_out, int out_size)
{
    const float* q   = (const float*)d_in[0];
    const float* k   = (const float*)d_in[1];
    const float* v   = (const float*)d_in[2];
    const float* Wq  = (const float*)d_in[3];
    const float* bq  = (const float*)d_in[4];
    const float* Wk  = (const float*)d_in[5];
    const float* bk  = (const float*)d_in[6];
    const float* Wv  = (const float*)d_in[7];
    const float* bv  = (const float*)d_in[8];
    const float* Wo  = (const float*)d_in[9];
    const float* bo  = (const float*)d_in[10];
    const int*   msk = (const int*)d_in[11];
    float* out = (float*)d_out;

    float *wtq, *wtk, *wtv, *xtq, *xtk, *xtv, *qh, *kh, *vh, *attn;
    cudaGetSymbolAddress((void**)&wtq, g_Wt_q);
    cudaGetSymbolAddress((void**)&wtk, g_Wt_k);
    cudaGetSymbolAddress((void**)&wtv, g_Wt_v);
    cudaGetSymbolAddress((void**)&xtq, g_Xt_q);
    cudaGetSymbolAddress((void**)&xtk, g_Xt_k);
    cudaGetSymbolAddress((void**)&xtv, g_Xt_v);
    cudaGetSymbolAddress((void**)&qh,  g_Qh);
    cudaGetSymbolAddress((void**)&kh,  g_Kh);
    cudaGetSymbolAddress((void**)&vh,  g_Vh);
    cudaGetSymbolAddress((void**)&attn, g_attn);

    // 1) tf32 prep: weight relayout + input transpose
    wprep_kernel<<<(1024 * 1024 * 9) / 256, 256>>>(Wq, wtq);
    wprep_kernel<<<(1024 * 1024 * 9) / 256, 256>>>(Wk, wtk);
    wprep_kernel<<<(1024 * 1024 * 9) / 256, 256>>>(Wv, wtv);
    xprep_kernel<<<(NB * 1024 * 1024) / 256, 256>>>(q, xtq);
    xprep_kernel<<<(NB * 1024 * 1024) / 256, 256>>>(k, xtk);
    xprep_kernel<<<(NB * 1024 * 1024) / 256, 256>>>(v, xtv);

    // 2) tensor-core convs -> head layout
    dim3 cg(8, 8, NB);
    conv_tc_kernel<<<cg, 256>>>(wtq, xtq, bq, qh);
    conv_tc_kernel<<<cg, 256>>>(wtk, xtk, bk, kh);
    conv_tc_kernel<<<cg, 256>>>(wtv, xtv, bv, vh);

    // 3) attention
    cudaFuncSetAttribute(attn_kernel,
                         cudaFuncAttributeMaxDynamicSharedMemorySize, 66560);
    attn_kernel<<<dim3(16, NHEAD, NB), 256, 66560>>>(qh, kh, vh, msk, attn);

    // 4) projection
    proj_kernel<<<dim3(16, 128), 256>>>(attn, Wo, bo, out);
}